// round 15
// baseline (speedup 1.0000x reference)
#include <cuda_runtime.h>
#include <cuda_bf16.h>
#include <cstdint>
#include <math.h>

#define TT 4096          // tokens
#define HH 1024          // hidden
#define FF 3584          // ffn dim
#define EE 8             // experts
#define SLOT_CAP (TT*2 + EE*128)   // 9216
#define NTILES (SLOT_CAP/128)      // 72
#define FBW 64                      // f-block width per CTA

// ---------------- small routing scratch only (~140KB of statics) ------------
__device__ int   d_sel[TT * 2];
__device__ float d_rw [TT * 2];
__device__ int   d_tile_expert[NTILES];
__device__ int   d_slot_token[SLOT_CAP];
__device__ float d_slot_w[SLOT_CAP];

// ---------------- dynamic smem layout (bytes) --------------------------------
// tok[128], rw[128], Xs[2][128][36], W1s[2][64][36], W3s[2][64][36], g[128][68]
// W2s[2][128][36] aliases the Xs region in stage B.
#define SM_TOK   0
#define SM_RW    512
#define SM_XS    1024
#define SM_W1S   37888
#define SM_W3S   56320
#define SM_G     74752
#define SMEM_TOTAL 109568

// ---------------- helpers ----------------------------------------------------
__device__ __forceinline__ uint32_t f2tf32(float f) {
    uint32_t r;
    asm("cvt.rna.tf32.f32 %0, %1;" : "=r"(r) : "f"(f));
    return r;
}
__device__ __forceinline__ void mma_tf32_16n8k8(float c[4],
                                                const uint32_t a[4],
                                                const uint32_t b[2]) {
    asm volatile(
        "mma.sync.aligned.m16n8k8.row.col.f32.tf32.tf32.f32 "
        "{%0,%1,%2,%3}, {%4,%5,%6,%7}, {%8,%9}, {%0,%1,%2,%3};"
        : "+f"(c[0]), "+f"(c[1]), "+f"(c[2]), "+f"(c[3])
        : "r"(a[0]), "r"(a[1]), "r"(a[2]), "r"(a[3]), "r"(b[0]), "r"(b[1]));
}

// ---------------- zero the output (it is poisoned before timing) ------------
__global__ void zero_out_kernel(float4* __restrict__ out) {
    int i = blockIdx.x * blockDim.x + threadIdx.x;
    if (i < TT * (HH / 4)) out[i] = make_float4(0.f, 0.f, 0.f, 0.f);
}

// ---------------- router: one warp per token (fp32 exact) -------------------
__global__ void router_kernel(const float* __restrict__ x,
                              const float* __restrict__ gw) {
    int gtid = blockIdx.x * blockDim.x + threadIdx.x;
    int t    = gtid >> 5;
    int lane = gtid & 31;
    if (t >= TT) return;
    const float* xt = x + (size_t)t * HH;

    float l[EE];
#pragma unroll
    for (int e = 0; e < EE; e++) {
        float s = 0.f;
        for (int h = lane; h < HH; h += 32) s += xt[h] * gw[e * HH + h];
#pragma unroll
        for (int o = 16; o; o >>= 1) s += __shfl_xor_sync(0xffffffffu, s, o);
        l[e] = s;
    }
    if (lane == 0) {
        int e0 = 0;
#pragma unroll
        for (int e = 1; e < EE; e++) if (l[e] > l[e0]) e0 = e;
        int e1 = -1;
#pragma unroll
        for (int e = 0; e < EE; e++)
            if (e != e0 && (e1 < 0 || l[e] > l[e1])) e1 = e;
        float w0 = 1.f / (1.f + expf(l[e1] - l[e0]));
        float w1 = 1.f - w0;
        d_sel[2*t] = e0; d_sel[2*t+1] = e1;
        d_rw [2*t] = w0; d_rw [2*t+1] = w1;
    }
}

// ---------------- build: counts + offsets + deterministic slots -------------
__global__ void build_kernel() {
    __shared__ int s_counts[EE];
    __shared__ int s_off[EE + 1];
    int tid = threadIdx.x;

    for (int i = tid; i < SLOT_CAP; i += 256) {
        d_slot_token[i] = -1;
        d_slot_w[i] = 0.f;
    }
    if (tid < EE) s_counts[tid] = 0;
    __syncthreads();

    for (int i = tid; i < 2 * TT; i += 256)
        atomicAdd(&s_counts[d_sel[i]], 1);
    __syncthreads();

    if (tid == 0) {
        int off = 0;
        for (int e = 0; e < EE; e++) {
            s_off[e] = off;
            int padded = (s_counts[e] + 127) & ~127;
            int t0 = off >> 7, nt = padded >> 7;
            for (int i = 0; i < nt; i++) d_tile_expert[t0 + i] = e;
            off += padded;
        }
        s_off[EE] = off;
        for (int i = off >> 7; i < NTILES; i++) d_tile_expert[i] = -1;
    }
    __syncthreads();

    int wid = tid >> 5, lane = tid & 31;
    if (wid < EE) {
        int base_off = s_off[wid];
        int pos = 0;
        for (int base = 0; base < 2 * TT; base += 32) {
            int i = base + lane;
            bool mine = (d_sel[i] == wid);
            unsigned m = __ballot_sync(0xffffffffu, mine);
            if (mine) {
                int rank = __popc(m & ((1u << lane) - 1u));
                int slot = base_off + pos + rank;
                d_slot_token[slot] = i >> 1;
                d_slot_w[slot]     = d_rw[i];
            }
            pos += __popc(m);
        }
    }
}

// ---------------- pipelined tf32 mma.sync megakernel ------------------------
// Block = (fblock 0..55 of 64 f-cols, slot-tile 0..71), 512 threads.
// Stage A: warps 0-7 compute h1 (32x32 tiles over 128x64), warps 8-15 h3.
//   W staging uses GROUP-LOCAL ids so each group covers its full 64x32 tile.
//   K=1024 in 32 chunks, 2-deep smem buffers, register prefetch, 1 bar/chunk.
// SwiGLU: h3 warps park c3 in g-smem; h1 warps combine -> g (tf32).
// Stage B: all 16 warps, out tile 128x128 per h-tile, K=64 in 2 chunks,
//   same 2-deep pipeline; atomicAdd into out.
__global__ __launch_bounds__(512, 1)
void moe_mma_kernel(const float* __restrict__ x,
                    const float* __restrict__ W1,
                    const float* __restrict__ W3,
                    const float* __restrict__ W2,
                    float* __restrict__ out) {
    int te = d_tile_expert[blockIdx.y];
    if (te < 0) return;
    int tileBase = blockIdx.y * 128;
    int fblock   = blockIdx.x;          // 0..55

    extern __shared__ char smem[];
    int*      rowtok = (int*)(smem + SM_TOK);
    float*    roww   = (float*)(smem + SM_RW);
    uint32_t* xsAll  = (uint32_t*)(smem + SM_XS);    // [2][128][36]
    uint32_t* w1All  = (uint32_t*)(smem + SM_W1S);   // [2][64][36]
    uint32_t* w3All  = (uint32_t*)(smem + SM_W3S);   // [2][64][36]
    uint32_t* gsm    = (uint32_t*)(smem + SM_G);     // [128][68]
    float*    gf     = (float*)gsm;
    uint32_t* w2All  = xsAll;                        // stage B alias [2][128][36]

    int tid  = threadIdx.x;
    int w    = tid >> 5;
    int lane = tid & 31;
    int lr4  = lane >> 2;          // 0..7
    int lc4  = lane & 3;           // 0..3

    if (tid < 128) {
        rowtok[tid] = d_slot_token[tileBase + tid];
        roww[tid]   = d_slot_w[tileBase + tid];
    }
    __syncthreads();

    const float4* X4  = (const float4*)x;
    const float4* W14 = (const float4*)W1;
    const float4* W34 = (const float4*)W3;
    const float4* W24 = (const float4*)W2;
    size_t wrowbase = (size_t)te * FF + (size_t)fblock * FBW;  // first f-row

    // X staging map: all 512 threads, rows 0..63 (xr0) and 64..127 (xr1)
    int xr0 = tid >> 3,  xc0 = tid & 7;
    int xr1 = xr0 + 64;
    int xt0 = rowtok[xr0], xt1 = rowtok[xr1];

    // W staging map: GROUP-LOCAL (256 threads per group cover 64 rows x 8 c4)
    int gtid = tid & 255;
    int wr   = gtid >> 2;          // 0..63
    int wc2  = gtid & 3;           // 0..3  (halves at wc2 and wc2+4)

    // stage A warp position: p = w&7 -> 4x2 grid of 32x32 tiles, matrix by w>=8
    int isW3 = (w >= 8);
    int p    = w & 7;
    int am0  = (p >> 1) << 5;      // 0,32,64,96
    int an0  = (p & 1) << 5;       // 0,32

    float4 px0, px1, pwa, pwb;     // prefetch regs

    auto LDA = [&](int kc) {
        px0 = make_float4(0.f,0.f,0.f,0.f);
        px1 = make_float4(0.f,0.f,0.f,0.f);
        if (xt0 >= 0) px0 = X4[(size_t)xt0 * 256 + kc * 8 + xc0];
        if (xt1 >= 0) px1 = X4[(size_t)xt1 * 256 + kc * 8 + xc0];
        const float4* src = isW3 ? W34 : W14;
        pwa = src[(wrowbase + wr) * 256 + kc * 8 + wc2];
        pwb = src[(wrowbase + wr) * 256 + kc * 8 + wc2 + 4];
    };
    auto STA = [&](int b) {
        uint32_t* xs = xsAll + b * (128 * 36);
        int o0 = xr0 * 36 + xc0 * 4;
        xs[o0+0] = f2tf32(px0.x); xs[o0+1] = f2tf32(px0.y);
        xs[o0+2] = f2tf32(px0.z); xs[o0+3] = f2tf32(px0.w);
        int o1 = xr1 * 36 + xc0 * 4;
        xs[o1+0] = f2tf32(px1.x); xs[o1+1] = f2tf32(px1.y);
        xs[o1+2] = f2tf32(px1.z); xs[o1+3] = f2tf32(px1.w);
        uint32_t* ws = (isW3 ? w3All : w1All) + b * (64 * 36);
        int oa = wr * 36 + wc2 * 4;
        ws[oa+0] = f2tf32(pwa.x); ws[oa+1] = f2tf32(pwa.y);
        ws[oa+2] = f2tf32(pwa.z); ws[oa+3] = f2tf32(pwa.w);
        int ob = wr * 36 + (wc2 + 4) * 4;
        ws[ob+0] = f2tf32(pwb.x); ws[ob+1] = f2tf32(pwb.y);
        ws[ob+2] = f2tf32(pwb.z); ws[ob+3] = f2tf32(pwb.w);
    };

    // ---------------- stage A ----------------
    float ca[2][4][4];
#pragma unroll
    for (int mt = 0; mt < 2; mt++)
#pragma unroll
        for (int nt = 0; nt < 4; nt++)
#pragma unroll
            for (int q = 0; q < 4; q++) ca[mt][nt][q] = 0.f;

    LDA(0); STA(0); __syncthreads();

    for (int kc = 0; kc < 32; kc++) {
        int b = kc & 1;
        if (kc < 31) LDA(kc + 1);
        uint32_t* xs = xsAll + b * (128 * 36);
        uint32_t* ws = (isW3 ? w3All : w1All) + b * (64 * 36);
#pragma unroll
        for (int ks = 0; ks < 4; ks++) {
            int k0 = ks * 8;
            uint32_t a[2][4];
#pragma unroll
            for (int mt = 0; mt < 2; mt++) {
                int rb = am0 + mt * 16;
                a[mt][0] = xs[(rb + lr4)     * 36 + k0 + lc4];
                a[mt][1] = xs[(rb + lr4 + 8) * 36 + k0 + lc4];
                a[mt][2] = xs[(rb + lr4)     * 36 + k0 + lc4 + 4];
                a[mt][3] = xs[(rb + lr4 + 8) * 36 + k0 + lc4 + 4];
            }
#pragma unroll
            for (int nt = 0; nt < 4; nt++) {
                int nb = an0 + nt * 8;
                uint32_t bf[2];
                bf[0] = ws[(nb + lr4) * 36 + k0 + lc4];
                bf[1] = ws[(nb + lr4) * 36 + k0 + lc4 + 4];
#pragma unroll
                for (int mt = 0; mt < 2; mt++)
                    mma_tf32_16n8k8(ca[mt][nt], a[mt], bf);
            }
        }
        if (kc < 31) STA(1 - b);
        __syncthreads();
    }

    // ---------------- SwiGLU exchange ----------------
    if (isW3) {   // park c3 as fp32 in g region
#pragma unroll
        for (int mt = 0; mt < 2; mt++) {
            int r0 = am0 + mt * 16 + lr4, r1 = r0 + 8;
#pragma unroll
            for (int nt = 0; nt < 4; nt++) {
                int cb = an0 + nt * 8 + lc4 * 2;
                gf[r0 * 68 + cb]     = ca[mt][nt][0];
                gf[r0 * 68 + cb + 1] = ca[mt][nt][1];
                gf[r1 * 68 + cb]     = ca[mt][nt][2];
                gf[r1 * 68 + cb + 1] = ca[mt][nt][3];
            }
        }
    }
    __syncthreads();
    if (!isW3) {  // g = silu(h1)*h3*rw -> tf32 (overwrite in place)
#pragma unroll
        for (int mt = 0; mt < 2; mt++) {
            int r0 = am0 + mt * 16 + lr4, r1 = r0 + 8;
            float w0 = roww[r0], w1r = roww[r1];
#pragma unroll
            for (int nt = 0; nt < 4; nt++) {
                int cb = an0 + nt * 8 + lc4 * 2;
                float h1, h3, g;
                h1 = ca[mt][nt][0]; h3 = gf[r0 * 68 + cb];
                g = (h1 / (1.f + expf(-h1))) * h3 * w0;
                gsm[r0 * 68 + cb]     = f2tf32(g);
                h1 = ca[mt][nt][1]; h3 = gf[r0 * 68 + cb + 1];
                g = (h1 / (1.f + expf(-h1))) * h3 * w0;
                gsm[r0 * 68 + cb + 1] = f2tf32(g);
                h1 = ca[mt][nt][2]; h3 = gf[r1 * 68 + cb];
                g = (h1 / (1.f + expf(-h1))) * h3 * w1r;
                gsm[r1 * 68 + cb]     = f2tf32(g);
                h1 = ca[mt][nt][3]; h3 = gf[r1 * 68 + cb + 1];
                g = (h1 / (1.f + expf(-h1))) * h3 * w1r;
                gsm[r1 * 68 + cb + 1] = f2tf32(g);
            }
        }
    }
    __syncthreads();

    // ---------------- stage B ----------------
    // warp tile over out: 4x4 grid of 32x32, per h-tile (8), K=64 in 2 chunks
    int bm0 = (w >> 2) << 5;
    int bn0 = (w & 3) << 5;
    int tokA[2], tokB[2];
#pragma unroll
    for (int mt = 0; mt < 2; mt++) {
        tokA[mt] = rowtok[bm0 + mt * 16 + lr4];
        tokB[mt] = rowtok[bm0 + mt * 16 + lr4 + 8];
    }

    float4 pb0, pb1;
    auto LDB = [&](int j) {
        int ht = j >> 1, kc = j & 1;
        size_t rowf4 = ((size_t)te * HH + ht * 128);
        pb0 = W24[(rowf4 + xr0) * 896 + fblock * 16 + kc * 8 + xc0];
        pb1 = W24[(rowf4 + xr1) * 896 + fblock * 16 + kc * 8 + xc0];
    };
    auto STB = [&](int b) {
        uint32_t* ws = w2All + b * (128 * 36);
        int o0 = xr0 * 36 + xc0 * 4;
        ws[o0+0] = f2tf32(pb0.x); ws[o0+1] = f2tf32(pb0.y);
        ws[o0+2] = f2tf32(pb0.z); ws[o0+3] = f2tf32(pb0.w);
        int o1 = xr1 * 36 + xc0 * 4;
        ws[o1+0] = f2tf32(pb1.x); ws[o1+1] = f2tf32(pb1.y);
        ws[o1+2] = f2tf32(pb1.z); ws[o1+3] = f2tf32(pb1.w);
    };

    float co[2][4][4];
    LDB(0); STB(0); __syncthreads();

    for (int j = 0; j < 16; j++) {
        int ht = j >> 1, kc = j & 1;
        int b = j & 1;
        if (kc == 0) {
#pragma unroll
            for (int mt = 0; mt < 2; mt++)
#pragma unroll
                for (int nt = 0; nt < 4; nt++)
#pragma unroll
                    for (int q = 0; q < 4; q++) co[mt][nt][q] = 0.f;
        }
        if (j < 15) LDB(j + 1);
        uint32_t* ws = w2All + b * (128 * 36);
#pragma unroll
        for (int ks = 0; ks < 4; ks++) {
            int kg = kc * 32 + ks * 8;
            int k0 = ks * 8;
            uint32_t a[2][4];
#pragma unroll
            for (int mt = 0; mt < 2; mt++) {
                int rb = bm0 + mt * 16;
                a[mt][0] = gsm[(rb + lr4)     * 68 + kg + lc4];
                a[mt][1] = gsm[(rb + lr4 + 8) * 68 + kg + lc4];
                a[mt][2] = gsm[(rb + lr4)     * 68 + kg + lc4 + 4];
                a[mt][3] = gsm[(rb + lr4 + 8) * 68 + kg + lc4 + 4];
            }
#pragma unroll
            for (int nt = 0; nt < 4; nt++) {
                int nb = bn0 + nt * 8;
                uint32_t bf[2];
                bf[0] = ws[(nb + lr4) * 36 + k0 + lc4];
                bf[1] = ws[(nb + lr4) * 36 + k0 + lc4 + 4];
#pragma unroll
                for (int mt = 0; mt < 2; mt++)
                    mma_tf32_16n8k8(co[mt][nt], a[mt], bf);
            }
        }
        if (j < 15) STB(1 - b);
        __syncthreads();

        if (kc == 1) {  // flush this h-tile
#pragma unroll
            for (int mt = 0; mt < 2; mt++) {
#pragma unroll
                for (int nt = 0; nt < 4; nt++) {
                    int hcol = ht * 128 + bn0 + nt * 8 + lc4 * 2;
                    if (tokA[mt] >= 0) {
                        float* dst = out + (size_t)tokA[mt] * HH + hcol;
                        atomicAdd(dst,     co[mt][nt][0]);
                        atomicAdd(dst + 1, co[mt][nt][1]);
                    }
                    if (tokB[mt] >= 0) {
                        float* dst = out + (size_t)tokB[mt] * HH + hcol;
                        atomicAdd(dst,     co[mt][nt][2]);
                        atomicAdd(dst + 1, co[mt][nt][3]);
                    }
                }
            }
        }
    }
}

extern "C" void kernel_launch(void* const* d_in, const int* in_sizes, int n_in,
                              void* d_out, int out_size) {
    const float* x  = nullptr;
    const float* gw = nullptr;
    const float* wbig[3] = {nullptr, nullptr, nullptr};
    int nb = 0;
    for (int i = 0; i < n_in; i++) {
        const float* p = (const float*)d_in[i];
        long long s = in_sizes[i];
        if (s == (long long)TT * HH || s == (long long)TT * HH * 4)      x = p;
        else if (s == (long long)EE * HH || s == (long long)EE * HH * 4) gw = p;
        else if (nb < 3) wbig[nb++] = p;
    }
    if (!x || !gw || nb < 3) {
        x  = (const float*)d_in[0];
        gw = (const float*)d_in[1];
        wbig[0] = (const float*)d_in[2];
        wbig[1] = (const float*)d_in[3];
        wbig[2] = (const float*)d_in[4];
    }
    const float* w1 = wbig[0];
    const float* w2 = wbig[1];
    const float* w3 = wbig[2];
    float* out = (float*)d_out;

    static int smem_set = 0;
    if (!smem_set) {
        cudaFuncSetAttribute(moe_mma_kernel,
                             cudaFuncAttributeMaxDynamicSharedMemorySize,
                             SMEM_TOTAL);
        smem_set = 1;
    }

    zero_out_kernel<<<(TT * (HH/4) + 255) / 256, 256>>>((float4*)out);
    router_kernel<<<(TT * 32 + 255) / 256, 256>>>(x, gw);
    build_kernel<<<1, 256>>>();

    dim3 grid(FF / FBW, NTILES);
    moe_mma_kernel<<<grid, 512, SMEM_TOTAL>>>(x, w1, w3, w2, out);
}

// round 16
// speedup vs baseline: 1.1127x; 1.1127x over previous
#include <cuda_runtime.h>
#include <cuda_bf16.h>
#include <cstdint>
#include <math.h>

#define TT 4096          // tokens
#define HH 1024          // hidden
#define FF 3584          // ffn dim
#define EE 8             // experts
#define SLOT_CAP (TT*2 + EE*128)   // 9216
#define NTILES (SLOT_CAP/128)      // 72
#define FBW 64                      // f-block width per CTA

// ---------------- small routing scratch only (~140KB of statics) ------------
__device__ int   d_sel[TT * 2];
__device__ float d_rw [TT * 2];
__device__ int   d_tile_expert[NTILES];
__device__ int   d_slot_token[SLOT_CAP];
__device__ float d_slot_w[SLOT_CAP];

// ---------------- dynamic smem layout (bytes) --------------------------------
// tok[128], rw[128], Xs[2][128][36] raw fp32, W1s[2][64][36], W3s[2][64][36],
// g[128][68] tf32. W2s[2][128][36] aliases Xs in stage B.
#define SM_TOK   0
#define SM_RW    512
#define SM_XS    1024
#define XSBUF    (128*36*4)                 // 18432
#define SM_W1S   (SM_XS + 2*XSBUF)          // 37888
#define WSBUF    (64*36*4)                  // 9216
#define SM_W3S   (SM_W1S + 2*WSBUF)         // 56320
#define SM_G     (SM_W3S + 2*WSBUF)         // 74752
#define SMEM_TOTAL (SM_G + 128*68*4)        // 109568 (~107KB) -> 2 CTAs/SM

// ---------------- helpers ----------------------------------------------------
__device__ __forceinline__ uint32_t smem_u32(const void* p) {
    uint32_t a;
    asm("{ .reg .u64 t; cvta.to.shared.u64 t, %1; cvt.u32.u64 %0, t; }"
        : "=r"(a) : "l"(p));
    return a;
}
__device__ __forceinline__ uint32_t f2tf32(float f) {
    uint32_t r;
    asm("cvt.rna.tf32.f32 %0, %1;" : "=r"(r) : "f"(f));
    return r;
}
__device__ __forceinline__ uint32_t u2tf32(uint32_t u) {
    return f2tf32(__uint_as_float(u));
}
__device__ __forceinline__ void mma_tf32_16n8k8(float c[4],
                                                const uint32_t a[4],
                                                const uint32_t b[2]) {
    asm volatile(
        "mma.sync.aligned.m16n8k8.row.col.f32.tf32.tf32.f32 "
        "{%0,%1,%2,%3}, {%4,%5,%6,%7}, {%8,%9}, {%0,%1,%2,%3};"
        : "+f"(c[0]), "+f"(c[1]), "+f"(c[2]), "+f"(c[3])
        : "r"(a[0]), "r"(a[1]), "r"(a[2]), "r"(a[3]), "r"(b[0]), "r"(b[1]));
}
__device__ __forceinline__ void cpa16(uint32_t dst, const void* src, int srcBytes) {
    asm volatile("cp.async.cg.shared.global [%0], [%1], 16, %2;"
                 :: "r"(dst), "l"(src), "r"(srcBytes) : "memory");
}
#define CPA_COMMIT() asm volatile("cp.async.commit_group;" ::: "memory")
#define CPA_WAIT1()  asm volatile("cp.async.wait_group 1;" ::: "memory")
#define CPA_WAIT0()  asm volatile("cp.async.wait_group 0;" ::: "memory")

// ---------------- zero the output (it is poisoned before timing) ------------
__global__ void zero_out_kernel(float4* __restrict__ out) {
    int i = blockIdx.x * blockDim.x + threadIdx.x;
    if (i < TT * (HH / 4)) out[i] = make_float4(0.f, 0.f, 0.f, 0.f);
}

// ---------------- router: one warp per token (fp32 exact) -------------------
__global__ void router_kernel(const float* __restrict__ x,
                              const float* __restrict__ gw) {
    int gtid = blockIdx.x * blockDim.x + threadIdx.x;
    int t    = gtid >> 5;
    int lane = gtid & 31;
    if (t >= TT) return;
    const float* xt = x + (size_t)t * HH;

    float l[EE];
#pragma unroll
    for (int e = 0; e < EE; e++) {
        float s = 0.f;
        for (int h = lane; h < HH; h += 32) s += xt[h] * gw[e * HH + h];
#pragma unroll
        for (int o = 16; o; o >>= 1) s += __shfl_xor_sync(0xffffffffu, s, o);
        l[e] = s;
    }
    if (lane == 0) {
        int e0 = 0;
#pragma unroll
        for (int e = 1; e < EE; e++) if (l[e] > l[e0]) e0 = e;
        int e1 = -1;
#pragma unroll
        for (int e = 0; e < EE; e++)
            if (e != e0 && (e1 < 0 || l[e] > l[e1])) e1 = e;
        float w0 = 1.f / (1.f + expf(l[e1] - l[e0]));
        float w1 = 1.f - w0;
        d_sel[2*t] = e0; d_sel[2*t+1] = e1;
        d_rw [2*t] = w0; d_rw [2*t+1] = w1;
    }
}

// ---------------- build: counts + offsets + deterministic slots -------------
__global__ void build_kernel() {
    __shared__ int s_counts[EE];
    __shared__ int s_off[EE + 1];
    int tid = threadIdx.x;

    for (int i = tid; i < SLOT_CAP; i += 256) {
        d_slot_token[i] = -1;
        d_slot_w[i] = 0.f;
    }
    if (tid < EE) s_counts[tid] = 0;
    __syncthreads();

    for (int i = tid; i < 2 * TT; i += 256)
        atomicAdd(&s_counts[d_sel[i]], 1);
    __syncthreads();

    if (tid == 0) {
        int off = 0;
        for (int e = 0; e < EE; e++) {
            s_off[e] = off;
            int padded = (s_counts[e] + 127) & ~127;
            int t0 = off >> 7, nt = padded >> 7;
            for (int i = 0; i < nt; i++) d_tile_expert[t0 + i] = e;
            off += padded;
        }
        s_off[EE] = off;
        for (int i = off >> 7; i < NTILES; i++) d_tile_expert[i] = -1;
    }
    __syncthreads();

    int wid = tid >> 5, lane = tid & 31;
    if (wid < EE) {
        int base_off = s_off[wid];
        int pos = 0;
        for (int base = 0; base < 2 * TT; base += 32) {
            int i = base + lane;
            bool mine = (d_sel[i] == wid);
            unsigned m = __ballot_sync(0xffffffffu, mine);
            if (mine) {
                int rank = __popc(m & ((1u << lane) - 1u));
                int slot = base_off + pos + rank;
                d_slot_token[slot] = i >> 1;
                d_slot_w[slot]     = d_rw[i];
            }
            pos += __popc(m);
        }
    }
}

// ---------------- 64x64-warp-tile tf32 megakernel ---------------------------
// Block = (fblock 0..55, slot-tile 0..71), 128 threads = 4 warps, 2 CTAs/SM.
// Stage A: warps 0-1 h1, warps 2-3 h3; warp tile 64m x 64f; K=1024 in 32
//   chunks staged raw-fp32 via cp.async (2-deep), cvt.rna at fragment load.
// SwiGLU: h3 park c3 fp32 -> g region; h1 combine -> g tf32.
// Stage B: 4 warps as 2m x 2h (64x64 tiles), h-tile 128 per iter (8 iters),
//   K=64 in 2 staged chunks; atomicAdd into out.
__global__ __launch_bounds__(128, 2)
void moe_mma_kernel(const float* __restrict__ x,
                    const float* __restrict__ W1,
                    const float* __restrict__ W3,
                    const float* __restrict__ W2,
                    float* __restrict__ out) {
    int te = d_tile_expert[blockIdx.y];
    if (te < 0) return;
    int tileBase = blockIdx.y * 128;
    int fblock   = blockIdx.x;          // 0..55

    extern __shared__ char smem[];
    uint32_t sb = smem_u32(smem);
    int*      rowtok = (int*)(smem + SM_TOK);
    float*    roww   = (float*)(smem + SM_RW);
    uint32_t* gsm    = (uint32_t*)(smem + SM_G);     // [128][68]
    float*    gf     = (float*)gsm;

    int tid  = threadIdx.x;
    int w    = tid >> 5;
    int lane = tid & 31;
    int lr4  = lane >> 2;          // 0..7
    int lc4  = lane & 3;           // 0..3

    rowtok[tid] = d_slot_token[tileBase + tid];
    roww[tid]   = d_slot_w[tileBase + tid];
    __syncthreads();

    size_t wrowbase = (size_t)te * FF + (size_t)fblock * FBW;

    // staging map: r8 = base row (stride 16), c4 = float4 col (0..7)
    int r8 = tid >> 3;             // 0..15
    int c4 = tid & 7;
    int xtok[8];
#pragma unroll
    for (int i = 0; i < 8; i++) xtok[i] = rowtok[r8 + i * 16];

    // stage A warp tile: group h1 = warps {0,1}, h3 = {2,3}; m0 = (w&1)*64
    int isW3 = (w >= 2);
    int m0   = (w & 1) << 6;

    const float* Wsrc = isW3 ? W3 : W1;
    uint32_t wsOff = isW3 ? SM_W3S : SM_W1S;

    auto issueA = [&](int kc, int b) {
        uint32_t xd = sb + SM_XS + b * XSBUF + (r8 * 36 + c4 * 4) * 4;
#pragma unroll
        for (int i = 0; i < 8; i++) {
            int tok = xtok[i];
            const float* src = (tok >= 0)
                ? (x + (size_t)tok * HH + kc * 32 + c4 * 4) : x;
            cpa16(xd + i * (16 * 36 * 4), src, tok >= 0 ? 16 : 0);
        }
        uint32_t w1d = sb + SM_W1S + b * WSBUF + (r8 * 36 + c4 * 4) * 4;
        const float* s1 = W1 + (wrowbase + r8) * HH + kc * 32 + c4 * 4;
#pragma unroll
        for (int i = 0; i < 4; i++)
            cpa16(w1d + i * (16 * 36 * 4), s1 + (size_t)i * 16 * HH, 16);
        uint32_t w3d = sb + SM_W3S + b * WSBUF + (r8 * 36 + c4 * 4) * 4;
        const float* s3 = W3 + (wrowbase + r8) * HH + kc * 32 + c4 * 4;
#pragma unroll
        for (int i = 0; i < 4; i++)
            cpa16(w3d + i * (16 * 36 * 4), s3 + (size_t)i * 16 * HH, 16);
        CPA_COMMIT();
    };

    // ---------------- stage A ----------------
    float ca[4][8][4];
#pragma unroll
    for (int mt = 0; mt < 4; mt++)
#pragma unroll
        for (int nt = 0; nt < 8; nt++)
#pragma unroll
            for (int q = 0; q < 4; q++) ca[mt][nt][q] = 0.f;

    issueA(0, 0);

    for (int kc = 0; kc < 32; kc++) {
        int b = kc & 1;
        if (kc < 31) { issueA(kc + 1, 1 - b); CPA_WAIT1(); }
        else         { CPA_WAIT0(); }
        __syncthreads();
        const uint32_t* xs = (const uint32_t*)(smem + SM_XS + b * XSBUF);
        const uint32_t* ws = (const uint32_t*)(smem + wsOff + b * WSBUF);
#pragma unroll
        for (int ks = 0; ks < 4; ks++) {
            int k0 = ks * 8;
            uint32_t a[4][4];
#pragma unroll
            for (int mt = 0; mt < 4; mt++) {
                int r = m0 + mt * 16 + lr4;
                a[mt][0] = u2tf32(xs[r * 36 + k0 + lc4]);
                a[mt][1] = u2tf32(xs[(r + 8) * 36 + k0 + lc4]);
                a[mt][2] = u2tf32(xs[r * 36 + k0 + lc4 + 4]);
                a[mt][3] = u2tf32(xs[(r + 8) * 36 + k0 + lc4 + 4]);
            }
#pragma unroll
            for (int nt = 0; nt < 8; nt++) {
                int nb = nt * 8 + lr4;
                uint32_t bf[2];
                bf[0] = u2tf32(ws[nb * 36 + k0 + lc4]);
                bf[1] = u2tf32(ws[nb * 36 + k0 + lc4 + 4]);
#pragma unroll
                for (int mt = 0; mt < 4; mt++)
                    mma_tf32_16n8k8(ca[mt][nt], a[mt], bf);
            }
        }
        __syncthreads();
    }

    // ---------------- SwiGLU exchange ----------------
    if (isW3) {   // park c3 fp32
#pragma unroll
        for (int mt = 0; mt < 4; mt++) {
            int r0 = m0 + mt * 16 + lr4, r1 = r0 + 8;
#pragma unroll
            for (int nt = 0; nt < 8; nt++) {
                int cb = nt * 8 + lc4 * 2;
                gf[r0 * 68 + cb]     = ca[mt][nt][0];
                gf[r0 * 68 + cb + 1] = ca[mt][nt][1];
                gf[r1 * 68 + cb]     = ca[mt][nt][2];
                gf[r1 * 68 + cb + 1] = ca[mt][nt][3];
            }
        }
    }
    __syncthreads();
    if (!isW3) {  // g = silu(h1)*h3*rw -> tf32 in place
#pragma unroll
        for (int mt = 0; mt < 4; mt++) {
            int r0 = m0 + mt * 16 + lr4, r1 = r0 + 8;
            float w0 = roww[r0], w1r = roww[r1];
#pragma unroll
            for (int nt = 0; nt < 8; nt++) {
                int cb = nt * 8 + lc4 * 2;
                float h1, h3, g;
                h1 = ca[mt][nt][0]; h3 = gf[r0 * 68 + cb];
                g = (h1 / (1.f + expf(-h1))) * h3 * w0;
                gsm[r0 * 68 + cb]     = f2tf32(g);
                h1 = ca[mt][nt][1]; h3 = gf[r0 * 68 + cb + 1];
                g = (h1 / (1.f + expf(-h1))) * h3 * w0;
                gsm[r0 * 68 + cb + 1] = f2tf32(g);
                h1 = ca[mt][nt][2]; h3 = gf[r1 * 68 + cb];
                g = (h1 / (1.f + expf(-h1))) * h3 * w1r;
                gsm[r1 * 68 + cb]     = f2tf32(g);
                h1 = ca[mt][nt][3]; h3 = gf[r1 * 68 + cb + 1];
                g = (h1 / (1.f + expf(-h1))) * h3 * w1r;
                gsm[r1 * 68 + cb + 1] = f2tf32(g);
            }
        }
    }
    __syncthreads();

    // ---------------- stage B ----------------
    int bm0 = (w >> 1) << 6;       // 0,64
    int bh0 = (w & 1) << 6;        // 0,64

    auto issueB = [&](int j, int b) {
        int hi = j >> 1, kc = j & 1;
        uint32_t dd = sb + SM_XS + b * XSBUF + (r8 * 36 + c4 * 4) * 4;
        const float* src = W2 + ((size_t)te * HH + hi * 128 + r8) * FF
                              + (size_t)fblock * FBW + kc * 32 + c4 * 4;
#pragma unroll
        for (int i = 0; i < 8; i++)
            cpa16(dd + i * (16 * 36 * 4), src + (size_t)i * 16 * FF, 16);
        CPA_COMMIT();
    };

    float co[4][8][4];
    issueB(0, 0);

    for (int j = 0; j < 16; j++) {
        int b = j & 1, hi = j >> 1, kc = j & 1;
        if (kc == 0) {
#pragma unroll
            for (int mt = 0; mt < 4; mt++)
#pragma unroll
                for (int nt = 0; nt < 8; nt++)
#pragma unroll
                    for (int q = 0; q < 4; q++) co[mt][nt][q] = 0.f;
        }
        if (j < 15) { issueB(j + 1, 1 - b); CPA_WAIT1(); }
        else        { CPA_WAIT0(); }
        __syncthreads();
        const uint32_t* ws = (const uint32_t*)(smem + SM_XS + b * XSBUF);
#pragma unroll
        for (int ks = 0; ks < 4; ks++) {
            int k0 = ks * 8;
            int kg = kc * 32 + k0;
            uint32_t a[4][4];
#pragma unroll
            for (int mt = 0; mt < 4; mt++) {
                int r = bm0 + mt * 16 + lr4;
                a[mt][0] = gsm[r * 68 + kg + lc4];
                a[mt][1] = gsm[(r + 8) * 68 + kg + lc4];
                a[mt][2] = gsm[r * 68 + kg + lc4 + 4];
                a[mt][3] = gsm[(r + 8) * 68 + kg + lc4 + 4];
            }
#pragma unroll
            for (int nt = 0; nt < 8; nt++) {
                int nb = bh0 + nt * 8 + lr4;
                uint32_t bf[2];
                bf[0] = u2tf32(ws[nb * 36 + k0 + lc4]);
                bf[1] = u2tf32(ws[nb * 36 + k0 + lc4 + 4]);
#pragma unroll
                for (int mt = 0; mt < 4; mt++)
                    mma_tf32_16n8k8(co[mt][nt], a[mt], bf);
            }
        }
        __syncthreads();

        if (kc == 1) {  // flush h-tile hi
#pragma unroll
            for (int mt = 0; mt < 4; mt++) {
                int rA = bm0 + mt * 16 + lr4;
                int tA = rowtok[rA], tB = rowtok[rA + 8];
#pragma unroll
                for (int nt = 0; nt < 8; nt++) {
                    int hcol = hi * 128 + bh0 + nt * 8 + lc4 * 2;
                    if (tA >= 0) {
                        float* dst = out + (size_t)tA * HH + hcol;
                        atomicAdd(dst,     co[mt][nt][0]);
                        atomicAdd(dst + 1, co[mt][nt][1]);
                    }
                    if (tB >= 0) {
                        float* dst = out + (size_t)tB * HH + hcol;
                        atomicAdd(dst,     co[mt][nt][2]);
                        atomicAdd(dst + 1, co[mt][nt][3]);
                    }
                }
            }
        }
    }
}

extern "C" void kernel_launch(void* const* d_in, const int* in_sizes, int n_in,
                              void* d_out, int out_size) {
    const float* x  = nullptr;
    const float* gw = nullptr;
    const float* wbig[3] = {nullptr, nullptr, nullptr};
    int nb = 0;
    for (int i = 0; i < n_in; i++) {
        const float* p = (const float*)d_in[i];
        long long s = in_sizes[i];
        if (s == (long long)TT * HH || s == (long long)TT * HH * 4)      x = p;
        else if (s == (long long)EE * HH || s == (long long)EE * HH * 4) gw = p;
        else if (nb < 3) wbig[nb++] = p;
    }
    if (!x || !gw || nb < 3) {
        x  = (const float*)d_in[0];
        gw = (const float*)d_in[1];
        wbig[0] = (const float*)d_in[2];
        wbig[1] = (const float*)d_in[3];
        wbig[2] = (const float*)d_in[4];
    }
    const float* w1 = wbig[0];
    const float* w2 = wbig[1];
    const float* w3 = wbig[2];
    float* out = (float*)d_out;

    static int smem_set = 0;
    if (!smem_set) {
        cudaFuncSetAttribute(moe_mma_kernel,
                             cudaFuncAttributeMaxDynamicSharedMemorySize,
                             SMEM_TOTAL);
        smem_set = 1;
    }

    zero_out_kernel<<<(TT * (HH/4) + 255) / 256, 256>>>((float4*)out);
    router_kernel<<<(TT * 32 + 255) / 256, 256>>>(x, gw);
    build_kernel<<<1, 256>>>();

    dim3 grid(FF / FBW, NTILES);
    moe_mma_kernel<<<grid, 128, SMEM_TOTAL>>>(x, w1, w3, w2, out);
}